// round 16
// baseline (speedup 1.0000x reference)
#include <cuda_runtime.h>
#include <cuda_bf16.h>
#include <cstdint>

// SumPooling / segment_sum with SORTED index (int32 or int64 — auto-detected).
// x: [N, 128] f32, index: [N] sorted, out: [16384, 128] f32.
//
// PROVEN-BEST two-kernel structure (82.2us @ R15; fused/persistent variants
// regressed — HW-scheduled 16384-CTA grid load-balances variable-length
// segments better than persistent CTAs):
//   K1: vectorized pass over index (4 elements/thread, streaming loads) ->
//       g_start[s] = lower_bound(index, s).
//   K2: one CTA per segment: 8 warps stream the segment's contiguous rows
//       (float4/lane, 2-deep MLP, __ldcs evict-first), smem cross-warp
//       reduce, single coalesced __stcs store. Runs at the B300 achieved-HBM
//       ceiling (~6.5 TB/s).

#define D_FEAT      128
#define N_SEGMENTS  16384
#define K1_THREADS  512
#define WARPS       8

__device__ int g_start[N_SEGMENTS + 1];

// JAX with x64 disabled silently downgrades int64 -> int32. Probe: read the
// middle of the buffer as int64. True int64 -> small value in [0,16384).
// int32 -> aliases two packed sorted int32s near the end -> huge.
__device__ __forceinline__ bool idx_is64(const void* __restrict__ idx, int n)
{
    long long probe = __ldg((const long long*)idx + ((n >> 1) - 1));
    return (probe >= 0 && probe < N_SEGMENTS);
}

// ---------------- K1: boundaries (4 elements per thread) ----------------

template <bool IS64>
__device__ __forceinline__ void boundaries_body(const void* __restrict__ index, int n)
{
    const int t    = blockIdx.x * K1_THREADS + threadIdx.x;
    const int base = t * 4;
    if (base >= n) return;

    int v[4];
    const int cnt = (n - base >= 4) ? 4 : (n - base);

    if (IS64) {
        const long long* p = (const long long*)index;
        if (cnt == 4) {
            longlong2 lo = __ldcs((const longlong2*)(p + base));
            longlong2 hi = __ldcs((const longlong2*)(p + base) + 1);
            v[0] = (int)lo.x; v[1] = (int)lo.y; v[2] = (int)hi.x; v[3] = (int)hi.y;
        } else {
            for (int k = 0; k < cnt; ++k) v[k] = (int)__ldg(p + base + k);
        }
    } else {
        const int* p = (const int*)index;
        if (cnt == 4) {
            int4 q = __ldcs((const int4*)(p + base));
            v[0] = q.x; v[1] = q.y; v[2] = q.z; v[3] = q.w;
        } else {
            for (int k = 0; k < cnt; ++k) v[k] = __ldg(p + base + k);
        }
    }

    int prev;
    if (base == 0) prev = -1;
    else prev = IS64 ? (int)__ldg((const long long*)index + base - 1)
                     : __ldg((const int*)index + base - 1);

    #pragma unroll
    for (int k = 0; k < 4; ++k) {
        if (k < cnt) {
            // start[s] = base+k for all s in (prev, v[k]]
            for (int s = prev + 1; s <= v[k]; ++s) g_start[s] = base + k;
            prev = v[k];
        }
    }

    if (base + cnt == n) {
        for (int s = prev + 1; s <= N_SEGMENTS; ++s) g_start[s] = n;
    }
}

__global__ __launch_bounds__(K1_THREADS)
void seg_boundaries_kernel(const void* __restrict__ index, int n)
{
    if (idx_is64(index, n)) boundaries_body<true >(index, n);
    else                    boundaries_body<false>(index, n);
}

// ---------------- K2: CTA per segment (proven design, streaming ld/st) ------

__global__ __launch_bounds__(WARPS * 32)
void segsum_kernel(const float* __restrict__ x, float* __restrict__ out)
{
    __shared__ float4 red[WARPS][32];

    const int seg  = blockIdx.x;
    const int w    = threadIdx.x >> 5;
    const int lane = threadIdx.x & 31;

    const int s0 = g_start[seg];
    const int s1 = g_start[seg + 1];

    const float4* __restrict__ x4 = reinterpret_cast<const float4*>(x);

    float4 a0 = make_float4(0.f, 0.f, 0.f, 0.f);
    float4 a1 = make_float4(0.f, 0.f, 0.f, 0.f);

    int r = s0 + w;
    for (; r + WARPS < s1; r += 2 * WARPS) {
        float4 v0 = __ldcs(x4 + (long long)r * 32 + lane);
        float4 v1 = __ldcs(x4 + (long long)(r + WARPS) * 32 + lane);
        a0.x += v0.x; a0.y += v0.y; a0.z += v0.z; a0.w += v0.w;
        a1.x += v1.x; a1.y += v1.y; a1.z += v1.z; a1.w += v1.w;
    }
    if (r < s1) {
        float4 v0 = __ldcs(x4 + (long long)r * 32 + lane);
        a0.x += v0.x; a0.y += v0.y; a0.z += v0.z; a0.w += v0.w;
    }
    a0.x += a1.x; a0.y += a1.y; a0.z += a1.z; a0.w += a1.w;

    red[w][lane] = a0;
    __syncthreads();

    if (threadIdx.x < 128) {
        const int t = threadIdx.x;
        float4 s = red[0][t & 31];
        #pragma unroll
        for (int ww = 1; ww < WARPS; ++ww) {
            float4 v = red[ww][t & 31];
            s.x += v.x; s.y += v.y; s.z += v.z; s.w += v.w;
        }
        float val = (t >> 5) == 0 ? s.x
                  : (t >> 5) == 1 ? s.y
                  : (t >> 5) == 2 ? s.z : s.w;
        // Evict-first store: output is written once, never re-read.
        __stcs(out + (long long)seg * D_FEAT + 4 * (t & 31) + (t >> 5), val);
    }
}

extern "C" void kernel_launch(void* const* d_in, const int* in_sizes, int n_in,
                              void* d_out, int out_size)
{
    const float* x     = (const float*)d_in[0];
    const void*  index = d_in[1];
    float*       out   = (float*)d_out;

    const int n_rows = in_sizes[0] / D_FEAT;   // 1,000,000

    const int k1_threads_total = (n_rows + 3) / 4;
    seg_boundaries_kernel<<<(k1_threads_total + K1_THREADS - 1) / K1_THREADS,
                            K1_THREADS>>>(index, n_rows);
    segsum_kernel<<<N_SEGMENTS, WARPS * 32>>>(x, out);
}

// round 17
// speedup vs baseline: 1.0362x; 1.0362x over previous
#include <cuda_runtime.h>
#include <cuda_bf16.h>
#include <cstdint>

// SumPooling / segment_sum with SORTED index (int32 or int64 — auto-detected).
// x: [N, 128] f32, index: [N] sorted, out: [16384, 128] f32.
//
// PROVEN-BEST two-kernel structure (82.2us best; fused/persistent variants
// regressed — HW-scheduled CTA-per-segment grid load-balances variable-length
// segments best):
//   K1: vectorized pass over index (4 elements/thread, streaming loads) ->
//       g_start[s] = lower_bound(index, s).
//   K2: one CTA per segment, 4 warps (128 threads): ~15 rows/warp halves the
//       epilogue share vs 8 warps; 16 CTAs/SM; float4/lane streaming loads
//       (__ldcs), 2-deep MLP, 4-way smem reduce, single coalesced 512B store.

#define D_FEAT      128
#define N_SEGMENTS  16384
#define K1_THREADS  512
#define WARPS       4
#define K2_THREADS  (WARPS * 32)

__device__ int g_start[N_SEGMENTS + 1];

// JAX with x64 disabled silently downgrades int64 -> int32. Probe: read the
// middle of the buffer as int64. True int64 -> small value in [0,16384).
// int32 -> aliases two packed sorted int32s near the end -> huge.
__device__ __forceinline__ bool idx_is64(const void* __restrict__ idx, int n)
{
    long long probe = __ldg((const long long*)idx + ((n >> 1) - 1));
    return (probe >= 0 && probe < N_SEGMENTS);
}

// ---------------- K1: boundaries (4 elements per thread) ----------------

template <bool IS64>
__device__ __forceinline__ void boundaries_body(const void* __restrict__ index, int n)
{
    const int t    = blockIdx.x * K1_THREADS + threadIdx.x;
    const int base = t * 4;
    if (base >= n) return;

    int v[4];
    const int cnt = (n - base >= 4) ? 4 : (n - base);

    if (IS64) {
        const long long* p = (const long long*)index;
        if (cnt == 4) {
            longlong2 lo = __ldcs((const longlong2*)(p + base));
            longlong2 hi = __ldcs((const longlong2*)(p + base) + 1);
            v[0] = (int)lo.x; v[1] = (int)lo.y; v[2] = (int)hi.x; v[3] = (int)hi.y;
        } else {
            for (int k = 0; k < cnt; ++k) v[k] = (int)__ldg(p + base + k);
        }
    } else {
        const int* p = (const int*)index;
        if (cnt == 4) {
            int4 q = __ldcs((const int4*)(p + base));
            v[0] = q.x; v[1] = q.y; v[2] = q.z; v[3] = q.w;
        } else {
            for (int k = 0; k < cnt; ++k) v[k] = __ldg(p + base + k);
        }
    }

    int prev;
    if (base == 0) prev = -1;
    else prev = IS64 ? (int)__ldg((const long long*)index + base - 1)
                     : __ldg((const int*)index + base - 1);

    #pragma unroll
    for (int k = 0; k < 4; ++k) {
        if (k < cnt) {
            // start[s] = base+k for all s in (prev, v[k]]
            for (int s = prev + 1; s <= v[k]; ++s) g_start[s] = base + k;
            prev = v[k];
        }
    }

    if (base + cnt == n) {
        for (int s = prev + 1; s <= N_SEGMENTS; ++s) g_start[s] = n;
    }
}

__global__ __launch_bounds__(K1_THREADS)
void seg_boundaries_kernel(const void* __restrict__ index, int n)
{
    if (idx_is64(index, n)) boundaries_body<true >(index, n);
    else                    boundaries_body<false>(index, n);
}

// ---------------- K2: CTA per segment, 4 warps ------------------------------

__global__ __launch_bounds__(K2_THREADS)
void segsum_kernel(const float* __restrict__ x, float* __restrict__ out)
{
    __shared__ float4 red[WARPS][32];

    const int seg  = blockIdx.x;
    const int w    = threadIdx.x >> 5;
    const int lane = threadIdx.x & 31;

    const int s0 = g_start[seg];
    const int s1 = g_start[seg + 1];

    const float4* __restrict__ x4 = reinterpret_cast<const float4*>(x);

    float4 a0 = make_float4(0.f, 0.f, 0.f, 0.f);
    float4 a1 = make_float4(0.f, 0.f, 0.f, 0.f);

    int r = s0 + w;
    for (; r + WARPS < s1; r += 2 * WARPS) {
        float4 v0 = __ldcs(x4 + (long long)r * 32 + lane);
        float4 v1 = __ldcs(x4 + (long long)(r + WARPS) * 32 + lane);
        a0.x += v0.x; a0.y += v0.y; a0.z += v0.z; a0.w += v0.w;
        a1.x += v1.x; a1.y += v1.y; a1.z += v1.z; a1.w += v1.w;
    }
    if (r < s1) {
        float4 v0 = __ldcs(x4 + (long long)r * 32 + lane);
        a0.x += v0.x; a0.y += v0.y; a0.z += v0.z; a0.w += v0.w;
    }
    a0.x += a1.x; a0.y += a1.y; a0.z += a1.z; a0.w += a1.w;

    red[w][lane] = a0;
    __syncthreads();

    // 128 threads: thread t reduces float4 group (t & 31) across the 4 warps
    // and extracts component (t >> 5). Single coalesced 512B store.
    {
        const int t = threadIdx.x;
        float4 s = red[0][t & 31];
        #pragma unroll
        for (int ww = 1; ww < WARPS; ++ww) {
            float4 v = red[ww][t & 31];
            s.x += v.x; s.y += v.y; s.z += v.z; s.w += v.w;
        }
        float val = (t >> 5) == 0 ? s.x
                  : (t >> 5) == 1 ? s.y
                  : (t >> 5) == 2 ? s.z : s.w;
        __stcs(out + (long long)seg * D_FEAT + 4 * (t & 31) + (t >> 5), val);
    }
}

extern "C" void kernel_launch(void* const* d_in, const int* in_sizes, int n_in,
                              void* d_out, int out_size)
{
    const float* x     = (const float*)d_in[0];
    const void*  index = d_in[1];
    float*       out   = (float*)d_out;

    const int n_rows = in_sizes[0] / D_FEAT;   // 1,000,000

    const int k1_threads_total = (n_rows + 3) / 4;
    seg_boundaries_kernel<<<(k1_threads_total + K1_THREADS - 1) / K1_THREADS,
                            K1_THREADS>>>(index, n_rows);
    segsum_kernel<<<N_SEGMENTS, K2_THREADS>>>(x, out);
}